// round 15
// baseline (speedup 1.0000x reference)
#include <cuda_runtime.h>

#define BB 4
#define XX 96
#define XYZ (XX*XX*XX)          // 884736
#define NVOX (BB*XYZ)           // 3538944
#define G 192
#define GW (G*G*G/32)           // 221184 words per batch
#define NROW (BB*XX*XX)         // 36864 (b,x,y) rows
#define NPACK (NROW*3)          // packed words
#define FLTMAX 3.402823466e38f

// ---------------- device scratch (zero-initialized at load; k_dilate
// re-clears g_occ and g_rand every launch, so each launch starts clean) -----
__device__ __align__(16) unsigned g_occ[BB][GW];   // 3.54 MB occupancy bitmap
__device__ __align__(16) unsigned g_pack[NPACK];   // sampled grid, bit-packed along z
__device__ __align__(16) unsigned g_rand[NPACK];   // rand_idx overlay bits
__device__ int g_tA[BB*3][XX];                     // corner0 (premul: x*1152 / y*6 / z raw)
__device__ int g_tB[BB*3][XX];                     // corner1
__device__ int g_tU[BB*3][XX];                     // f>0 flag

// ---------------- K1: scatter (4 pts/thread) + setup + rand overlay ----------------
__global__ void __launch_bounds__(1024)
k_scatter(const float* __restrict__ coords,
          const float* __restrict__ T,
          const float* __restrict__ Tinv,
          const int* __restrict__ sparse, int npts, int nperb,
          const int* __restrict__ ridx, int na) {
    __shared__ float s_off[12], s_hi[12], s_T[64], s_Ti[64];
    __shared__ float s_minl[12], s_maxl[12], s_msg[3];
    __shared__ float s_mv[12], s_sv[3], s_pb[12], s_vs[12];
    const int tid = threadIdx.x;
    if (tid < 12) {
        s_off[tid] = coords[(size_t)tid * XYZ];
        s_hi[tid]  = coords[(size_t)tid * XYZ + (XYZ - 1)];
    } else if (tid >= 64 && tid < 128) {
        s_T[tid - 64]  = T[tid - 64];
        s_Ti[tid - 64] = Tinv[tid - 64];
    }
    __syncthreads();
    if (tid < 12) {
        s_minl[tid] = fminf(s_off[tid], s_hi[tid]);
        s_maxl[tid] = fmaxf(s_off[tid], s_hi[tid]);
    }
    __syncthreads();
    if (tid < 3) {
        float m = -FLTMAX;
        for (int b = 0; b < BB; b++)
            m = fmaxf(m, (s_maxl[b * 3 + tid] + 0.08f) - s_minl[b * 3 + tid]);
        s_msg[tid] = m;
    }
    if (tid >= 32 && tid < 44) {          // minvox in parallel warp
        int q = tid - 32, b = q / 3, i = q % 3;
        float s = 0.0f;
        for (int j = 0; j < 3; j++) s += s_Ti[b * 16 + i * 4 + j] * s_minl[b * 3 + j];
        s += s_Ti[b * 16 + i * 4 + 3];
        s_mv[q] = fmaxf(floorf(s), 0.0f);
    }
    __syncthreads();
    if (tid < 3) {
        float m = -FLTMAX;
        for (int b = 0; b < BB; b++) {
            float s = 0.0f;
            for (int j = 0; j < 3; j++) s += s_Ti[b * 16 + tid * 4 + j] * s_msg[j];
            m = fmaxf(m, s);
        }
        s_sv[tid] = ceilf(m);
    }
    __syncthreads();
    if (blockIdx.x == 0) {
        if (tid < 12) {
            int b = tid / 3, i = tid % 3;
            float s = 0.0f;
            for (int j = 0; j < 3; j++) s += s_T[b * 16 + i * 4 + j] * s_mv[b * 3 + j];
            s += s_T[b * 16 + i * 4 + 3];
            s_pb[tid] = s;
            float e = 0.0f;
            for (int j = 0; j < 3; j++) e += s_T[b * 16 + i * 4 + j] * s_sv[j];
            s_vs[tid] = e / s_sv[i];
        }
        __syncthreads();
        for (int q = tid; q < 12 * XX; q += 1024) {
            int i  = q % XX;
            int ch = q / XX;
            int c  = ch % 3;
            float val = (float)i * 0.08f + s_off[ch];    // bit-exact meshgrid value
            float p  = (val - s_pb[ch]) / s_vs[ch] - 0.5f;
            float p0 = floorf(p);
            float f  = p - p0;
            int ip = (int)p0;
            int i0 = min(max(ip, 0), G - 1);
            int i1 = min(max(ip + 1, 0), G - 1);
            int mul = (c == 0) ? 1152 : (c == 1) ? 6 : 1;
            g_tA[ch][i] = i0 * mul;
            g_tB[ch][i] = i1 * mul;
            g_tU[ch][i] = (f > 0.0f) ? 1 : 0;
        }
    }
    const int t = blockIdx.x * 1024 + tid;
    if (t < na) {
        int b = t % BB;
        int x = ridx[t];
        int y = ridx[na + t];
        int z = ridx[2 * na + t];
        int p = (b * XX + x) * XX + y;
        atomicOr(&g_rand[p * 3 + (z >> 5)], 1u << (z & 31));
    }
    int p0 = t * 4;
    if (p0 < npts) {
        const int4* s4 = (const int4*)(sparse + (size_t)p0 * 3);
        int4 a = s4[0], bq = s4[1], cq = s4[2];
        int pts[4][3] = {{a.x, a.y, a.z}, {a.w, bq.x, bq.y},
                         {bq.z, bq.w, cq.x}, {cq.y, cq.z, cq.w}};
        unsigned sv0 = (unsigned)(int)s_sv[0], sv1 = (unsigned)(int)s_sv[1],
                 sv2 = (unsigned)(int)s_sv[2];
        int b = p0 / nperb;   // nperb % 4 == 0 -> all 4 points same batch
        int m0 = (int)s_mv[b * 3 + 0], m1 = (int)s_mv[b * 3 + 1], m2 = (int)s_mv[b * 3 + 2];
        unsigned* occ = g_occ[b];
#pragma unroll
        for (int i = 0; i < 4; i++) {
            if (p0 + i >= npts) break;
            unsigned se0 = (unsigned)(pts[i][0] - m0);   // <0 wraps huge -> fails <sv
            unsigned se1 = (unsigned)(pts[i][1] - m1);
            unsigned se2 = (unsigned)(pts[i][2] - m2);
            if (se0 >= sv0 || se1 >= sv1 || se2 >= sv2) continue;
            int id = ((int)min(se0, (unsigned)(G - 1)) * G + (int)min(se1, (unsigned)(G - 1))) * G
                   + (int)min(se2, (unsigned)(G - 1));
            atomicOr(&occ[id >> 5], 1u << (id & 31));
        }
    }
}

// ---------------- K2: table-driven boolean trilinear sample ----------------
__global__ void k_sample(float* __restrict__ occ_out) {
    int v = blockIdx.x * blockDim.x + threadIdx.x;   // grid sized exactly NVOX
    int b = v / XYZ;
    int r = v - b * XYZ;
    int z = r % XX;
    int y = (r / XX) % XX;
    int x = r / (XX * XX);
    int bc = b * 3;
    int wx0 = g_tA[bc][x],     wx1 = g_tB[bc][x];     bool ux = g_tU[bc][x];
    int wy0 = g_tA[bc + 1][y], wy1 = g_tB[bc + 1][y]; bool uy = g_tU[bc + 1][y];
    int iz0 = g_tA[bc + 2][z], iz1 = g_tB[bc + 2][z]; bool uz = g_tU[bc + 2][z];
    const unsigned* occ = g_occ[b];
    int zw0 = iz0 >> 5; unsigned mz0 = 1u << (iz0 & 31);
    int zw1 = iz1 >> 5; unsigned mz1 = 1u << (iz1 & 31);
    bool samew = (zw1 == zw0);
    unsigned acc = 0;
#define PROBE(base) do {                                             \
        unsigned w0 = occ[(base) + zw0];                             \
        acc |= w0 & mz0;                                             \
        if (uz) {                                                    \
            unsigned w1 = samew ? w0 : occ[(base) + zw1];            \
            acc |= w1 & mz1;                                         \
        }                                                            \
    } while (0)
    PROBE(wx0 + wy0);
    if (uy) PROBE(wx0 + wy1);
    if (ux) {
        PROBE(wx1 + wy0);
        if (uy) PROBE(wx1 + wy1);
    }
#undef PROBE
    bool any = acc != 0;
    occ_out[v] = any ? 1.0f : 0.0f;
    unsigned w = __ballot_sync(0xFFFFFFFFu, any);
    if ((v & 31) == 0) g_pack[v >> 5] = w;
}

// ---------------- K3: fused 5x5x5 OR-dilation + rand + expand, per-float4 ----------------
// 884736 threads; 8-lane groups own one output word (p,k). Lane q<5 handles
// dy=q-2: ORs words k-1,k,k+1 over the 5 dx-neighbors, applies z-dilation
// (zdil distributes over OR); lane 5 contributes the rand word. 3 shfl-OR
// rounds reduce the group; each lane expands+stores one float4.
__global__ void __launch_bounds__(256)
k_dilate(float* __restrict__ mask) {
    int j = blockIdx.x * 256 + threadIdx.x;   // grid sized exactly NVOX/4
    int q   = j & 7;                          // float4 slot within word
    int t24 = j % 24;                         // k*8+q
    int p   = j / 24;                         // (b,x,y) row
    int k   = t24 >> 3;
    int y = p % XX;
    int x = (p / XX) % XX;
    int b = p / (XX * XX);
    unsigned r = 0;
    if (q < 5) {
        int yy = y + q - 2;
        if (yy >= 0 && yy < XX) {
            unsigned am = 0, ac = 0, ap = 0;
            bool hm = (k > 0), hp = (k < 2);
#pragma unroll
            for (int dx = -2; dx <= 2; dx++) {
                int xx = x + dx;
                if (xx < 0 || xx >= XX) continue;
                const unsigned* qq = &g_pack[((b * XX + xx) * XX + yy) * 3 + k];
                ac |= qq[0];
                if (hm) am |= qq[-1];
                if (hp) ap |= qq[1];
            }
            r = ac | (ac << 1) | (ac << 2) | (ac >> 1) | (ac >> 2)
              | (ap << 31) | (ap << 30)      // low z-bits of next word
              | (am >> 31) | (am >> 30);     // high z-bits of prev word
        }
    } else if (q == 5) {
        r = g_rand[p * 3 + k];
    }
    r |= __shfl_xor_sync(0xFFFFFFFFu, r, 1);
    r |= __shfl_xor_sync(0xFFFFFFFFu, r, 2);
    r |= __shfl_xor_sync(0xFFFFFFFFu, r, 4);
    int sh = q * 4;
    float4 f;
    f.x = (r >> (sh + 0)) & 1u ? 1.0f : 0.0f;
    f.y = (r >> (sh + 1)) & 1u ? 1.0f : 0.0f;
    f.z = (r >> (sh + 2)) & 1u ? 1.0f : 0.0f;
    f.w = (r >> (sh + 3)) & 1u ? 1.0f : 0.0f;
    ((float4*)(mask + (size_t)p * XX + k * 32))[q] = f;
    // clears for next launch: rand (lane 6; after lane-5 read in warp program
    // order) and one g_occ word per thread (NVOX/4 threads = BB*GW words)
    if (q == 6) g_rand[p * 3 + k] = 0;
    ((unsigned*)g_occ)[j] = 0;
}

extern "C" void kernel_launch(void* const* d_in, const int* in_sizes, int n_in,
                              void* d_out, int out_size) {
    const float* coords = (const float*)d_in[0];
    const float* T      = (const float*)d_in[1];
    const float* Tinv   = (const float*)d_in[2];
    const int*   sparse = (const int*)d_in[3];
    // d_in[4] = conv_w (all-ones 5^3 box; boolean dilation is exact)
    const int*   ridx   = (const int*)d_in[5];

    int npts  = in_sizes[3] / 3;       // B*N
    int nperb = npts / BB;             // N
    int na    = in_sizes[5] / 3;       // NUM_ADD

    float* occ_out  = (float*)d_out;
    float* mask_out = occ_out + (size_t)BB * XYZ;

    int sb = (npts / 4 + 1023) / 1024;             // scatter blocks (1024 thr)

    k_scatter<<<sb, 1024>>>(coords, T, Tinv, sparse, npts, nperb, ridx, na);
    k_sample<<<NVOX / 256, 256>>>(occ_out);
    k_dilate<<<(NVOX / 4) / 256, 256>>>(mask_out);
}

// round 16
// speedup vs baseline: 1.0798x; 1.0798x over previous
#include <cuda_runtime.h>

#define BB 4
#define XX 96
#define XYZ (XX*XX*XX)          // 884736
#define NVOX (BB*XYZ)           // 3538944
#define G 192
#define GW (G*G*G/32)           // 221184 words per batch
#define NROW (BB*XX*XX)         // 36864 (b,x,y) rows
#define NPACK (NROW*3)          // packed words
#define FLTMAX 3.402823466e38f

// ---------------- device scratch (zero-initialized at load; k_dilate_x
// re-clears g_occ/g_rand every launch, so each launch starts clean) ----------
__device__ __align__(16) unsigned g_occ[BB][GW];   // 3.54 MB occupancy bitmap
__device__ __align__(16) unsigned g_pack[NPACK];   // sampled grid, bit-packed along z
__device__ __align__(16) unsigned g_py[NPACK];     // after y+z dilation
__device__ __align__(16) unsigned g_rand[NPACK];   // rand_idx overlay bits
__device__ int g_tA[BB*3][XX];                     // corner0 (premul: x*1152 / y*6 / z raw)
__device__ int g_tB[BB*3][XX];                     // corner1
__device__ int g_tU[BB*3][XX];                     // f>0 flag

// ---------------- K1: scatter (4 pts/thread) + setup + rand overlay ----------------
__global__ void __launch_bounds__(1024)
k_scatter(const float* __restrict__ coords,
          const float* __restrict__ T,
          const float* __restrict__ Tinv,
          const int* __restrict__ sparse, int npts, int nperb,
          const int* __restrict__ ridx, int na) {
    __shared__ float s_off[12], s_T[64], s_Ti[64];
    __shared__ float s_minl[12], s_maxl[12], s_msg[3];
    __shared__ float s_mv[12], s_sv[3], s_pb[12], s_vs[12];
    const int tid = threadIdx.x;
    // stage A: loads; corner lanes fold min/max locally (no extra barrier)
    if (tid < 12) {
        float v0 = coords[(size_t)tid * XYZ];
        float v1 = coords[(size_t)tid * XYZ + (XYZ - 1)];
        s_off[tid]  = v0;
        s_minl[tid] = fminf(v0, v1);
        s_maxl[tid] = fmaxf(v0, v1);
    } else if (tid >= 64 && tid < 128) {
        s_T[tid - 64]  = T[tid - 64];
        s_Ti[tid - 64] = Tinv[tid - 64];
    }
    __syncthreads();                       // sync 1
    // stage B (parallel warps): msg + minvox
    if (tid < 3) {
        float m = -FLTMAX;
        for (int b = 0; b < BB; b++)
            m = fmaxf(m, (s_maxl[b * 3 + tid] + 0.08f) - s_minl[b * 3 + tid]);
        s_msg[tid] = m;
    }
    if (tid >= 32 && tid < 44) {
        int q = tid - 32, b = q / 3, i = q % 3;
        float s = 0.0f;
        for (int j = 0; j < 3; j++) s += s_Ti[b * 16 + i * 4 + j] * s_minl[b * 3 + j];
        s += s_Ti[b * 16 + i * 4 + 3];
        s_mv[q] = fmaxf(floorf(s), 0.0f);
    }
    __syncthreads();                       // sync 2
    if (tid < 3) {
        float m = -FLTMAX;
        for (int b = 0; b < BB; b++) {
            float s = 0.0f;
            for (int j = 0; j < 3; j++) s += s_Ti[b * 16 + tid * 4 + j] * s_msg[j];
            m = fmaxf(m, s);
        }
        s_sv[tid] = ceilf(m);
    }
    __syncthreads();                       // sync 3
    if (blockIdx.x == 0) {
        if (tid < 12) {
            int b = tid / 3, i = tid % 3;
            float s = 0.0f;
            for (int j = 0; j < 3; j++) s += s_T[b * 16 + i * 4 + j] * s_mv[b * 3 + j];
            s += s_T[b * 16 + i * 4 + 3];
            s_pb[tid] = s;
            float e = 0.0f;
            for (int j = 0; j < 3; j++) e += s_T[b * 16 + i * 4 + j] * s_sv[j];
            s_vs[tid] = e / s_sv[i];
        }
        __syncthreads();                   // sync 4 (block 0 only)
        for (int q = tid; q < 12 * XX; q += 1024) {
            int i  = q % XX;
            int ch = q / XX;
            int c  = ch % 3;
            float val = (float)i * 0.08f + s_off[ch];    // bit-exact meshgrid value
            float p  = (val - s_pb[ch]) / s_vs[ch] - 0.5f;
            float p0 = floorf(p);
            float f  = p - p0;
            int ip = (int)p0;
            int i0 = min(max(ip, 0), G - 1);
            int i1 = min(max(ip + 1, 0), G - 1);
            int mul = (c == 0) ? 1152 : (c == 1) ? 6 : 1;
            g_tA[ch][i] = i0 * mul;
            g_tB[ch][i] = i1 * mul;
            g_tU[ch][i] = (f > 0.0f) ? 1 : 0;
        }
    }
    const int t = blockIdx.x * 1024 + tid;
    if (t < na) {
        int b = t % BB;
        int x = ridx[t];
        int y = ridx[na + t];
        int z = ridx[2 * na + t];
        int p = (b * XX + x) * XX + y;
        atomicOr(&g_rand[p * 3 + (z >> 5)], 1u << (z & 31));
    }
    // scatter 4 points/thread; npts % 4 == 0 -> no per-point tail checks
    int p0 = t * 4;
    if (p0 < npts) {
        const int4* s4 = (const int4*)(sparse + (size_t)p0 * 3);
        int4 a = s4[0], bq = s4[1], cq = s4[2];
        int pts[4][3] = {{a.x, a.y, a.z}, {a.w, bq.x, bq.y},
                         {bq.z, bq.w, cq.x}, {cq.y, cq.z, cq.w}};
        unsigned sv0 = (unsigned)(int)s_sv[0], sv1 = (unsigned)(int)s_sv[1],
                 sv2 = (unsigned)(int)s_sv[2];
        int b = p0 / nperb;   // nperb % 4 == 0 -> all 4 points same batch
        int m0 = (int)s_mv[b * 3 + 0], m1 = (int)s_mv[b * 3 + 1], m2 = (int)s_mv[b * 3 + 2];
        unsigned* occ = g_occ[b];
#pragma unroll
        for (int i = 0; i < 4; i++) {
            unsigned se0 = (unsigned)(pts[i][0] - m0);   // <0 wraps huge -> fails <sv
            unsigned se1 = (unsigned)(pts[i][1] - m1);
            unsigned se2 = (unsigned)(pts[i][2] - m2);
            if (se0 >= sv0 || se1 >= sv1 || se2 >= sv2) continue;
            int id = ((int)min(se0, (unsigned)(G - 1)) * G + (int)min(se1, (unsigned)(G - 1))) * G
                   + (int)min(se2, (unsigned)(G - 1));
            atomicOr(&occ[id >> 5], 1u << (id & 31));
        }
    }
}

// ---------------- K2: table-driven boolean trilinear sample ----------------
__global__ void k_sample(float* __restrict__ occ_out) {
    int v = blockIdx.x * blockDim.x + threadIdx.x;   // grid sized exactly NVOX
    int b = v / XYZ;
    int r = v - b * XYZ;
    int z = r % XX;
    int y = (r / XX) % XX;
    int x = r / (XX * XX);
    int bc = b * 3;
    int wx0 = g_tA[bc][x],     wx1 = g_tB[bc][x];     bool ux = g_tU[bc][x];
    int wy0 = g_tA[bc + 1][y], wy1 = g_tB[bc + 1][y]; bool uy = g_tU[bc + 1][y];
    int iz0 = g_tA[bc + 2][z], iz1 = g_tB[bc + 2][z]; bool uz = g_tU[bc + 2][z];
    const unsigned* occ = g_occ[b];
    int zw0 = iz0 >> 5; unsigned mz0 = 1u << (iz0 & 31);
    int zw1 = iz1 >> 5; unsigned mz1 = 1u << (iz1 & 31);
    bool samew = (zw1 == zw0);
    unsigned acc = 0;
#define PROBE(base) do {                                             \
        unsigned w0 = occ[(base) + zw0];                             \
        acc |= w0 & mz0;                                             \
        if (uz) {                                                    \
            unsigned w1 = samew ? w0 : occ[(base) + zw1];            \
            acc |= w1 & mz1;                                         \
        }                                                            \
    } while (0)
    PROBE(wx0 + wy0);
    if (uy) PROBE(wx0 + wy1);
    if (ux) {
        PROBE(wx1 + wy0);
        if (uy) PROBE(wx1 + wy1);
    }
#undef PROBE
    bool any = acc != 0;
    occ_out[v] = any ? 1.0f : 0.0f;
    unsigned w = __ballot_sync(0xFFFFFFFFu, any);
    if ((v & 31) == 0) g_pack[v >> 5] = w;
}

// ---------------- K3: y-OR + z-bitshift dilation (per row) ----------------
__global__ void k_dilate_yz() {
    int p = blockIdx.x * blockDim.x + threadIdx.x;
    if (p >= NROW) return;
    int y  = p % XX;
    int xr = p / XX;                  // b*XX + x
    unsigned a0 = 0, a1 = 0, a2 = 0;
#pragma unroll
    for (int dy = -2; dy <= 2; dy++) {
        int yy = y + dy;
        if (yy < 0 || yy >= XX) continue;
        const unsigned* q = &g_pack[(xr * XX + yy) * 3];
        a0 |= q[0]; a1 |= q[1]; a2 |= q[2];
    }
    unsigned r0 = a0 | (a0 << 1) | (a0 << 2) | (a0 >> 1) | (a0 >> 2)
                | (a1 << 31) | (a1 << 30);
    unsigned r1 = a1 | (a1 << 1) | (a1 << 2) | (a1 >> 1) | (a1 >> 2)
                | (a0 >> 31) | (a0 >> 30) | (a2 << 31) | (a2 << 30);
    unsigned r2 = a2 | (a2 << 1) | (a2 << 2) | (a2 >> 1) | (a2 >> 2)
                | (a1 >> 31) | (a1 >> 30);
    unsigned* o = &g_py[p * 3];
    o[0] = r0; o[1] = r1; o[2] = r2;
}

// ---------------- K4: x-OR + rand + expand, per-float4 warp-cooperative ----------------
// 884736 threads; 8-lane groups own one packed word. Lane q<5 loads x-neighbor q,
// lane 5 loads rand word; width-8 shfl-OR reduce; each lane stores one float4.
__global__ void __launch_bounds__(256)
k_dilate_x(float* __restrict__ mask) {
    int j = blockIdx.x * 256 + threadIdx.x;   // grid sized exactly NVOX/4
    int q   = j & 7;                          // float4 slot within word
    int t24 = j % 24;                         // k*8+q
    int p   = j / 24;                         // (b,x,y) row
    int k   = t24 >> 3;
    int y = p % XX;
    int x = (p / XX) % XX;
    int b = p / (XX * XX);
    unsigned part = 0;
    if (q < 5) {
        int xx = x + q - 2;
        if (xx >= 0 && xx < XX)
            part = g_py[(((b * XX + xx) * XX) + y) * 3 + k];
    } else if (q == 5) {
        part = g_rand[p * 3 + k];
    }
    part |= __shfl_xor_sync(0xFFFFFFFFu, part, 1);
    part |= __shfl_xor_sync(0xFFFFFFFFu, part, 2);
    part |= __shfl_xor_sync(0xFFFFFFFFu, part, 4);
    int sh = q * 4;
    float4 f;
    f.x = (part >> (sh + 0)) & 1u ? 1.0f : 0.0f;
    f.y = (part >> (sh + 1)) & 1u ? 1.0f : 0.0f;
    f.z = (part >> (sh + 2)) & 1u ? 1.0f : 0.0f;
    f.w = (part >> (sh + 3)) & 1u ? 1.0f : 0.0f;
    ((float4*)(mask + (size_t)p * XX + k * 32))[q] = f;
    // clears for next launch: rand (lane 6 of each group; after lane-5 read in
    // this warp's program order) and one g_occ word per thread (884736 = BB*GW)
    if (q == 6) g_rand[p * 3 + k] = 0;
    ((unsigned*)g_occ)[j] = 0;
}

extern "C" void kernel_launch(void* const* d_in, const int* in_sizes, int n_in,
                              void* d_out, int out_size) {
    const float* coords = (const float*)d_in[0];
    const float* T      = (const float*)d_in[1];
    const float* Tinv   = (const float*)d_in[2];
    const int*   sparse = (const int*)d_in[3];
    // d_in[4] = conv_w (all-ones 5^3 box; boolean dilation is exact)
    const int*   ridx   = (const int*)d_in[5];

    int npts  = in_sizes[3] / 3;       // B*N
    int nperb = npts / BB;             // N
    int na    = in_sizes[5] / 3;       // NUM_ADD

    float* occ_out  = (float*)d_out;
    float* mask_out = occ_out + (size_t)BB * XYZ;

    int sb = (npts / 4 + 1023) / 1024;             // scatter blocks (1024 thr)

    k_scatter<<<sb, 1024>>>(coords, T, Tinv, sparse, npts, nperb, ridx, na);
    k_sample<<<NVOX / 256, 256>>>(occ_out);
    k_dilate_yz<<<(NROW + 127) / 128, 128>>>();
    k_dilate_x<<<(NVOX / 4) / 256, 256>>>(mask_out);
}

// round 17
// speedup vs baseline: 1.1160x; 1.0335x over previous
#include <cuda_runtime.h>

#define BB 4
#define XX 96
#define XYZ (XX*XX*XX)          // 884736
#define NVOX (BB*XYZ)           // 3538944
#define G 192
#define GW (G*G*G/32)           // 221184 words per batch
#define NROW (BB*XX*XX)         // 36864 (b,x,y) rows
#define NPACK (NROW*3)          // packed words
#define FLTMAX 3.402823466e38f

// ---------------- device scratch (zero-initialized at load; k_dilate_x
// re-clears g_occ/g_rand every launch, so each launch starts clean) ----------
__device__ __align__(16) unsigned g_occ[BB][GW];   // 3.54 MB occupancy bitmap
__device__ __align__(16) unsigned g_py[NPACK];     // after y+z dilation
__device__ __align__(16) unsigned g_rand[NPACK];   // rand_idx overlay bits
__device__ int g_tA[BB*3][XX];                     // corner0 (premul: x*1152 / y*6 / z raw)
__device__ int g_tB[BB*3][XX];                     // corner1
__device__ int g_tU[BB*3][XX];                     // f>0 flag

// ---------------- K1: scatter (4 pts/thread) + setup + rand overlay ----------------
__global__ void __launch_bounds__(1024)
k_scatter(const float* __restrict__ coords,
          const float* __restrict__ T,
          const float* __restrict__ Tinv,
          const int* __restrict__ sparse, int npts, int nperb,
          const int* __restrict__ ridx, int na) {
    __shared__ float s_off[12], s_T[64], s_Ti[64];
    __shared__ float s_minl[12], s_maxl[12], s_msg[3];
    __shared__ float s_mv[12], s_sv[3], s_pb[12], s_vs[12];
    const int tid = threadIdx.x;
    if (tid < 12) {
        float v0 = coords[(size_t)tid * XYZ];
        float v1 = coords[(size_t)tid * XYZ + (XYZ - 1)];
        s_off[tid]  = v0;
        s_minl[tid] = fminf(v0, v1);
        s_maxl[tid] = fmaxf(v0, v1);
    } else if (tid >= 64 && tid < 128) {
        s_T[tid - 64]  = T[tid - 64];
        s_Ti[tid - 64] = Tinv[tid - 64];
    }
    __syncthreads();                       // sync 1
    if (tid < 3) {
        float m = -FLTMAX;
        for (int b = 0; b < BB; b++)
            m = fmaxf(m, (s_maxl[b * 3 + tid] + 0.08f) - s_minl[b * 3 + tid]);
        s_msg[tid] = m;
    }
    if (tid >= 32 && tid < 44) {
        int q = tid - 32, b = q / 3, i = q % 3;
        float s = 0.0f;
        for (int j = 0; j < 3; j++) s += s_Ti[b * 16 + i * 4 + j] * s_minl[b * 3 + j];
        s += s_Ti[b * 16 + i * 4 + 3];
        s_mv[q] = fmaxf(floorf(s), 0.0f);
    }
    __syncthreads();                       // sync 2
    if (tid < 3) {
        float m = -FLTMAX;
        for (int b = 0; b < BB; b++) {
            float s = 0.0f;
            for (int j = 0; j < 3; j++) s += s_Ti[b * 16 + tid * 4 + j] * s_msg[j];
            m = fmaxf(m, s);
        }
        s_sv[tid] = ceilf(m);
    }
    __syncthreads();                       // sync 3
    if (blockIdx.x == 0) {
        if (tid < 12) {
            int b = tid / 3, i = tid % 3;
            float s = 0.0f;
            for (int j = 0; j < 3; j++) s += s_T[b * 16 + i * 4 + j] * s_mv[b * 3 + j];
            s += s_T[b * 16 + i * 4 + 3];
            s_pb[tid] = s;
            float e = 0.0f;
            for (int j = 0; j < 3; j++) e += s_T[b * 16 + i * 4 + j] * s_sv[j];
            s_vs[tid] = e / s_sv[i];
        }
        __syncthreads();                   // sync 4 (block 0 only)
        for (int q = tid; q < 12 * XX; q += 1024) {
            int i  = q % XX;
            int ch = q / XX;
            int c  = ch % 3;
            float val = (float)i * 0.08f + s_off[ch];    // bit-exact meshgrid value
            float p  = (val - s_pb[ch]) / s_vs[ch] - 0.5f;
            float p0 = floorf(p);
            float f  = p - p0;
            int ip = (int)p0;
            int i0 = min(max(ip, 0), G - 1);
            int i1 = min(max(ip + 1, 0), G - 1);
            int mul = (c == 0) ? 1152 : (c == 1) ? 6 : 1;
            g_tA[ch][i] = i0 * mul;
            g_tB[ch][i] = i1 * mul;
            g_tU[ch][i] = (f > 0.0f) ? 1 : 0;
        }
    }
    const int t = blockIdx.x * 1024 + tid;
    if (t < na) {
        int b = t % BB;
        int x = ridx[t];
        int y = ridx[na + t];
        int z = ridx[2 * na + t];
        int p = (b * XX + x) * XX + y;
        atomicOr(&g_rand[p * 3 + (z >> 5)], 1u << (z & 31));
    }
    // scatter 4 points/thread; npts % 4 == 0 -> no per-point tail checks
    int p0 = t * 4;
    if (p0 < npts) {
        const int4* s4 = (const int4*)(sparse + (size_t)p0 * 3);
        int4 a = s4[0], bq = s4[1], cq = s4[2];
        int pts[4][3] = {{a.x, a.y, a.z}, {a.w, bq.x, bq.y},
                         {bq.z, bq.w, cq.x}, {cq.y, cq.z, cq.w}};
        unsigned sv0 = (unsigned)(int)s_sv[0], sv1 = (unsigned)(int)s_sv[1],
                 sv2 = (unsigned)(int)s_sv[2];
        int b = p0 / nperb;   // nperb % 4 == 0 -> all 4 points same batch
        int m0 = (int)s_mv[b * 3 + 0], m1 = (int)s_mv[b * 3 + 1], m2 = (int)s_mv[b * 3 + 2];
        unsigned* occ = g_occ[b];
#pragma unroll
        for (int i = 0; i < 4; i++) {
            unsigned se0 = (unsigned)(pts[i][0] - m0);   // <0 wraps huge -> fails <sv
            unsigned se1 = (unsigned)(pts[i][1] - m1);
            unsigned se2 = (unsigned)(pts[i][2] - m2);
            if (se0 >= sv0 || se1 >= sv1 || se2 >= sv2) continue;
            int id = ((int)min(se0, (unsigned)(G - 1)) * G + (int)min(se1, (unsigned)(G - 1))) * G
                   + (int)min(se2, (unsigned)(G - 1));
            atomicOr(&occ[id >> 5], 1u << (id & 31));
        }
    }
}

// ---------------- K2: sample + y/z-dilation fused (slab block per (b,x)) ----------------
// 384 blocks x 1024 threads. Each block owns the (y,z) plane of one (b,x):
// stage 1 samples 9216 voxels (9 iters), ballots into 288 smem words; stage 2
// does the block-local y-OR + z-bitshift and writes g_py.
__global__ void __launch_bounds__(1024)
k_sample_yz(float* __restrict__ occ_out) {
    __shared__ unsigned spack[XX * 3];            // 288 words: (y, k)
    int bx = blockIdx.x;                          // b*XX + x
    int b  = bx / XX;
    int x  = bx - b * XX;
    int bc = b * 3;
    int wx0 = g_tA[bc][x], wx1 = g_tB[bc][x];
    bool ux = g_tU[bc][x] != 0;
    const unsigned* occ = g_occ[b];
    int tid = threadIdx.x;
    float* outp = occ_out + (size_t)bx * (XX * XX);
#pragma unroll
    for (int s = 0; s < 9; s++) {
        int v = s * 1024 + tid;                   // [0, 9216); warp = one z-word
        int y = v / XX;
        int z = v - y * XX;
        int wy0 = g_tA[bc + 1][y], wy1 = g_tB[bc + 1][y]; bool uy = g_tU[bc + 1][y];
        int iz0 = g_tA[bc + 2][z], iz1 = g_tB[bc + 2][z]; bool uz = g_tU[bc + 2][z];
        int zw0 = iz0 >> 5; unsigned mz0 = 1u << (iz0 & 31);
        int zw1 = iz1 >> 5; unsigned mz1 = 1u << (iz1 & 31);
        bool samew = (zw1 == zw0);
        unsigned acc = 0;
#define PROBE(base) do {                                             \
            unsigned w0 = occ[(base) + zw0];                         \
            acc |= w0 & mz0;                                         \
            if (uz) {                                                \
                unsigned w1 = samew ? w0 : occ[(base) + zw1];        \
                acc |= w1 & mz1;                                     \
            }                                                        \
        } while (0)
        PROBE(wx0 + wy0);
        if (uy) PROBE(wx0 + wy1);
        if (ux) {
            PROBE(wx1 + wy0);
            if (uy) PROBE(wx1 + wy1);
        }
#undef PROBE
        bool any = acc != 0;
        outp[v] = any ? 1.0f : 0.0f;
        unsigned wbal = __ballot_sync(0xFFFFFFFFu, any);
        if ((v & 31) == 0) spack[v >> 5] = wbal;  // 96=3*32 -> warp==one word
    }
    __syncthreads();
    // stage 2: y-OR (5-window) + z-bitshift; one thread per (y,k) word
    if (tid < XX * 3) {
        int y = tid / 3, k = tid - y * 3;
        unsigned am = 0, ac = 0, ap = 0;
        bool hm = (k > 0), hp = (k < 2);
#pragma unroll
        for (int dy = -2; dy <= 2; dy++) {
            int yy = y + dy;
            if (yy < 0 || yy >= XX) continue;
            const unsigned* q = &spack[yy * 3 + k];
            ac |= q[0];
            if (hm) am |= q[-1];
            if (hp) ap |= q[1];
        }
        unsigned r = ac | (ac << 1) | (ac << 2) | (ac >> 1) | (ac >> 2)
                   | (ap << 31) | (ap << 30)     // low z-bits of next word
                   | (am >> 31) | (am >> 30);    // high z-bits of prev word
        g_py[(bx * XX + y) * 3 + k] = r;
    }
}

// ---------------- K3: x-OR + rand + expand, per-float4 warp-cooperative ----------------
// 884736 threads; 8-lane groups own one packed word. Lane q<5 loads x-neighbor q,
// lane 5 loads rand word; width-8 shfl-OR reduce; each lane stores one float4.
__global__ void __launch_bounds__(256)
k_dilate_x(float* __restrict__ mask) {
    int j = blockIdx.x * 256 + threadIdx.x;   // grid sized exactly NVOX/4
    int q   = j & 7;                          // float4 slot within word
    int t24 = j % 24;                         // k*8+q
    int p   = j / 24;                         // (b,x,y) row
    int k   = t24 >> 3;
    int y = p % XX;
    int x = (p / XX) % XX;
    int b = p / (XX * XX);
    unsigned part = 0;
    if (q < 5) {
        int xx = x + q - 2;
        if (xx >= 0 && xx < XX)
            part = g_py[(((b * XX + xx) * XX) + y) * 3 + k];
    } else if (q == 5) {
        part = g_rand[p * 3 + k];
    }
    part |= __shfl_xor_sync(0xFFFFFFFFu, part, 1);
    part |= __shfl_xor_sync(0xFFFFFFFFu, part, 2);
    part |= __shfl_xor_sync(0xFFFFFFFFu, part, 4);
    int sh = q * 4;
    float4 f;
    f.x = (part >> (sh + 0)) & 1u ? 1.0f : 0.0f;
    f.y = (part >> (sh + 1)) & 1u ? 1.0f : 0.0f;
    f.z = (part >> (sh + 2)) & 1u ? 1.0f : 0.0f;
    f.w = (part >> (sh + 3)) & 1u ? 1.0f : 0.0f;
    ((float4*)(mask + (size_t)p * XX + k * 32))[q] = f;
    // clears for next launch: rand (lane 6 of each group; after lane-5 read in
    // this warp's program order) and one g_occ word per thread (884736 = BB*GW)
    if (q == 6) g_rand[p * 3 + k] = 0;
    ((unsigned*)g_occ)[j] = 0;
}

extern "C" void kernel_launch(void* const* d_in, const int* in_sizes, int n_in,
                              void* d_out, int out_size) {
    const float* coords = (const float*)d_in[0];
    const float* T      = (const float*)d_in[1];
    const float* Tinv   = (const float*)d_in[2];
    const int*   sparse = (const int*)d_in[3];
    // d_in[4] = conv_w (all-ones 5^3 box; boolean dilation is exact)
    const int*   ridx   = (const int*)d_in[5];

    int npts  = in_sizes[3] / 3;       // B*N
    int nperb = npts / BB;             // N
    int na    = in_sizes[5] / 3;       // NUM_ADD

    float* occ_out  = (float*)d_out;
    float* mask_out = occ_out + (size_t)BB * XYZ;

    int sb = (npts / 4 + 1023) / 1024;             // scatter blocks (1024 thr)

    k_scatter<<<sb, 1024>>>(coords, T, Tinv, sparse, npts, nperb, ridx, na);
    k_sample_yz<<<BB * XX, 1024>>>(occ_out);
    k_dilate_x<<<(NVOX / 4) / 256, 256>>>(mask_out);
}